// round 2
// baseline (speedup 1.0000x reference)
#include <cuda_runtime.h>

// QuantumRegression: 1024 x 14-qubit statevector sim, 3 layers (Rot per wire + CNOT ring),
// <Z_w> features, linear head.
//
// R2: NT=512 (occ 12.5%->25%); tile pass split into two single-matrix passes to keep
// register peak under 128/thread (one Mat4 live at a time).

#define NW   14
#define DIM  16384
#define NT   512

typedef unsigned long long u64;

__device__ float4 g_mats[21][16];   // per wire-pair 4x4: {ur, ur, -ui, ui}

// ---------------- setup: build fused 4x4 gate matrices ----------------

struct cpx { float re, im; };
__device__ __forceinline__ cpx cmul(cpx a, cpx b){
    cpx r; r.re = a.re*b.re - a.im*b.im; r.im = a.re*b.im + a.im*b.re; return r;
}

__device__ void rotmat(const float* p, cpx U[2][2]){
    float cx = cosf(0.5f*p[0]), sx = sinf(0.5f*p[0]);
    float cy = cosf(0.5f*p[1]), sy = sinf(0.5f*p[1]);
    float cz = cosf(0.5f*p[2]), sz = sinf(0.5f*p[2]);
    cpx r00 = { cy*cx,  sy*sx};
    cpx r01 = {-sy*cx, -cy*sx};
    cpx r10 = { sy*cx, -cy*sx};
    cpx r11 = { cy*cx, -sy*sx};
    cpx e0 = {cz, -sz}, e1 = {cz, sz};
    U[0][0] = cmul(e0, r00); U[0][1] = cmul(e0, r01);
    U[1][0] = cmul(e1, r10); U[1][1] = cmul(e1, r11);
}

__global__ void setup_mats(const float* __restrict__ vp){
    int pid = threadIdx.x;
    if (pid >= 21) return;
    int l = pid / 7, k = pid % 7;
    cpx Ua[2][2], Ub[2][2];
    rotmat(vp + (l*NW + 2*k    )*3, Ua);
    rotmat(vp + (l*NW + 2*k + 1)*3, Ub);
    #pragma unroll
    for (int i = 0; i < 2; i++)
    #pragma unroll
    for (int j = 0; j < 2; j++)
    #pragma unroll
    for (int a = 0; a < 2; a++)
    #pragma unroll
    for (int c = 0; c < 2; c++){
        cpx m = cmul(Ua[i][a], Ub[j][c]);
        g_mats[pid][(2*i + j)*4 + (2*a + c)] = make_float4(m.re, m.re, -m.im, m.im);
    }
}

// ---------------- packed f32x2 helpers ----------------

__device__ __forceinline__ u64 pk2(float lo, float hi){
    u64 r; asm("mov.b64 %0, {%1,%2};" : "=l"(r) : "f"(lo), "f"(hi)); return r;
}
__device__ __forceinline__ void upk2(u64 v, float& lo, float& hi){
    asm("mov.b64 {%0,%1}, %2;" : "=f"(lo), "=f"(hi) : "l"(v));
}
__device__ __forceinline__ u64 swp2(u64 v){
    u64 r;
    asm("{ .reg .b32 a,b; mov.b64 {a,b}, %1; mov.b64 %0, {b,a}; }" : "=l"(r) : "l"(v));
    return r;
}
__device__ __forceinline__ u64 f2(u64 a, u64 b, u64 c){
    u64 r; asm("fma.rn.f32x2 %0, %1, %2, %3;" : "=l"(r) : "l"(a), "l"(b), "l"(c)); return r;
}
__device__ __forceinline__ u64 m2(u64 a, u64 b){
    u64 r; asm("mul.rn.f32x2 %0, %1, %2;" : "=l"(r) : "l"(a), "l"(b)); return r;
}

struct Mat4 { u64 u[16], n[16]; };

__device__ __forceinline__ void loadmat(Mat4& M, int pair){
    #pragma unroll
    for (int e = 0; e < 16; e++){
        float4 f = __ldg(&g_mats[pair][e]);
        M.u[e] = pk2(f.x, f.y);
        M.n[e] = pk2(f.z, f.w);
    }
}

// out_s = sum_t M[s,t] * in_t   (complex, packed (re,im))
__device__ __forceinline__ void mv4(const Mat4& M, const u64 v[4], const u64 vs[4], u64 o[4]){
    #pragma unroll
    for (int s = 0; s < 4; s++){
        u64 a = m2(M.u[4*s+0], v[0]);
        a = f2(M.n[4*s+0], vs[0], a);
        #pragma unroll
        for (int t = 1; t < 4; t++){
            a = f2(M.u[4*s+t], v[t], a);
            a = f2(M.n[4*s+t], vs[t], a);
        }
        o[s] = a;
    }
}

// ---------------- CNOT-ring permutation (GF2 linear) ----------------
__device__ __forceinline__ int pfwd(int i){
    int y = i;
    y ^= y >> 1; y ^= y >> 2; y ^= y >> 4; y ^= y >> 8;
    return (y & 0x1FFF) ^ ((((y ^ (i >> 13)) & 1) << 13));
}
__device__ __forceinline__ int pinv(int o){
    int t = o ^ (o >> 1);
    return (t & 0x1FFF) ^ (o & 0x2000) ^ ((o & 1) ? 0x3000 : 0);
}

// ---------------- passes ----------------

// two-wire in-place pass, insert position p (>= 4)
__device__ __forceinline__ void pass2w(float2* psi, const Mat4& M, int p, int t){
    const int lowmask = (1 << p) - 1;
    const int step = lowmask + 1;
    #pragma unroll 4
    for (int j = 0; j < DIM/4/NT; j++){
        int gid  = t + NT*j;                 // 0..4095
        int low  = gid & lowmask;
        int idx0 = ((gid ^ low) << 2) | low; // insert 2 bits at position p
        u64 v[4], vs[4], o[4];
        #pragma unroll
        for (int s = 0; s < 4; s++){
            float2 a = psi[idx0 + s*step];
            v[s]  = pk2(a.x, a.y);
            vs[s] = pk2(a.y, a.x);
        }
        mv4(M, v, vs, o);
        #pragma unroll
        for (int s = 0; s < 4; s++){
            float lo, hi; upk2(o[s], lo, hi);
            psi[idx0 + s*step] = make_float2(lo, hi);
        }
    }
}

// tile pass over 16 consecutive amps, single 4x4 matrix.
// HI=1: groups stride 4 (wires 10,11 / bits 3,2); HI=0: stride 1 (wires 12,13 / bits 1,0).
template<int HI>
__device__ __forceinline__ void tilepass1(float2* psi, const Mat4& M, int t){
    float4* p4 = reinterpret_cast<float4*>(psi);
    const int rot = t & 7;
    #pragma unroll 1
    for (int tt = 0; tt < DIM/16/NT; tt++){
        int tile = t + NT*tt;                // 0..1023
        u64 amp[16];
        #pragma unroll
        for (int r = 0; r < 8; r++){
            int rr = (r + rot) & 7;
            float4 q = p4[tile*8 + rr];
            amp[2*rr]   = pk2(q.x, q.y);
            amp[2*rr+1] = pk2(q.z, q.w);
        }
        #pragma unroll
        for (int q = 0; q < 4; q++){
            u64 v[4], vs[4], o[4];
            #pragma unroll
            for (int s = 0; s < 4; s++){
                int idx = HI ? ((s<<2)|q) : ((q<<2)|s);
                v[s] = amp[idx]; vs[s] = swp2(v[s]);
            }
            mv4(M, v, vs, o);
            #pragma unroll
            for (int s = 0; s < 4; s++){
                int idx = HI ? ((s<<2)|q) : ((q<<2)|s);
                amp[idx] = o[s];
            }
        }
        #pragma unroll
        for (int r = 0; r < 8; r++){
            int rr = (r + rot) & 7;
            float l0,h0,l1,h1;
            upk2(amp[2*rr],   l0, h0);
            upk2(amp[2*rr+1], l1, h1);
            p4[tile*8 + rr] = make_float4(l0, h0, l1, h1);
        }
    }
}

// materialize CNOT-ring permutation: whole-CTA register staging
__device__ __forceinline__ void permpass(float2* psi, int t){
    float2 tmp[DIM/NT];
    #pragma unroll
    for (int j = 0; j < DIM/NT; j++){
        int o = t + NT*j;
        tmp[j] = psi[pinv(o)];
    }
    __syncthreads();
    #pragma unroll
    for (int j = 0; j < DIM/NT; j++)
        psi[t + NT*j] = tmp[j];
}

// ---------------- main kernel ----------------

__global__ void __launch_bounds__(NT, 1)
qsim_kernel(const float* __restrict__ sr, const float* __restrict__ si,
            const float* __restrict__ hw, const float* __restrict__ hb,
            float* __restrict__ out)
{
    extern __shared__ float2 psi[];
    const int t = threadIdx.x;
    const int b = blockIdx.x;

    // layer 0, pair 0 (wires 0,1 / position 12) fused with global load
    {
        Mat4 M; loadmat(M, 0);
        const float* srb = sr + (size_t)b * DIM;
        const float* sib = si + (size_t)b * DIM;
        #pragma unroll 2
        for (int j = 0; j < DIM/4/NT; j++){
            int gid = t + NT*j;
            u64 v[4], vs[4], o[4];
            #pragma unroll
            for (int s = 0; s < 4; s++){
                float re = __ldg(srb + gid + (s << 12));
                float im = __ldg(sib + gid + (s << 12));
                v[s] = pk2(re, im); vs[s] = pk2(im, re);
            }
            mv4(M, v, vs, o);
            #pragma unroll
            for (int s = 0; s < 4; s++){
                float lo, hi; upk2(o[s], lo, hi);
                psi[gid + (s << 12)] = make_float2(lo, hi);
            }
        }
    }
    __syncthreads();

    #pragma unroll 1
    for (int l = 0; l < 3; l++){
        int kstart = (l == 0) ? 1 : 0;
        #pragma unroll 1
        for (int k = kstart; k < 5; k++){
            Mat4 M; loadmat(M, l*7 + k);
            pass2w(psi, M, 12 - 2*k, t);
            __syncthreads();
        }
        {
            Mat4 A; loadmat(A, l*7 + 5);
            tilepass1<1>(psi, A, t);
            __syncthreads();
        }
        {
            Mat4 B; loadmat(B, l*7 + 6);
            tilepass1<0>(psi, B, t);
            __syncthreads();
        }
        if (l < 2){
            permpass(psi, t);
            __syncthreads();
        }
    }

    // measurement: fold final CNOT-ring permutation via o = P(i); signed prob sums
    float zs[NW];
    #pragma unroll
    for (int w = 0; w < NW; w++) zs[w] = 0.f;
    #pragma unroll 8
    for (int j = 0; j < DIM/NT; j++){
        int i = t + NT*j;
        float2 a = psi[i];
        float pr = a.x*a.x + a.y*a.y;
        int o = pfwd(i);
        #pragma unroll
        for (int w = 0; w < NW; w++)
            zs[w] += (o & (1 << (13 - w))) ? -pr : pr;
    }
    // warp reduce
    #pragma unroll
    for (int off = 16; off > 0; off >>= 1)
        #pragma unroll
        for (int w = 0; w < NW; w++)
            zs[w] += __shfl_down_sync(0xffffffffu, zs[w], off);
    __syncthreads();                       // all psi reads done; reuse as scratch
    float* red = (float*)psi;
    int lane = t & 31, wid = t >> 5;
    const int NWARP = NT/32;
    if (lane == 0){
        #pragma unroll
        for (int w = 0; w < NW; w++) red[w*NWARP + wid] = zs[w];
    }
    __syncthreads();
    if (t == 0){
        float acc = __ldg(hb);
        #pragma unroll
        for (int w = 0; w < NW; w++){
            float f = 0.f;
            #pragma unroll
            for (int r = 0; r < NWARP; r++) f += red[w*NWARP + r];
            acc += f * __ldg(hw + w);
        }
        out[b] = acc;
    }
}

// ---------------- launch ----------------

extern "C" void kernel_launch(void* const* d_in, const int* in_sizes, int n_in,
                              void* d_out, int out_size)
{
    const float* sr = (const float*)d_in[0];
    const float* si = (const float*)d_in[1];
    const float* vp = (const float*)d_in[2];
    const float* hw = (const float*)d_in[3];
    const float* hb = (const float*)d_in[4];
    float* out = (float*)d_out;

    cudaFuncSetAttribute(qsim_kernel, cudaFuncAttributeMaxDynamicSharedMemorySize, 131072);

    setup_mats<<<1, 32>>>(vp);

    int B = in_sizes[0] / DIM;
    qsim_kernel<<<B, NT, 131072>>>(sr, si, hw, hb, out);
}

// round 3
// speedup vs baseline: 1.6526x; 1.6526x over previous
#include <cuda_runtime.h>

// QuantumRegression: 1024 x 14-qubit statevector sim, 3 layers (Rot per wire + CNOT ring),
// <Z_w> features, linear head.
//
// R3: NT=256 (R2's NT=512 spilled). Multi-stage register-tile passes:
//   T1: pairs (0,1),(2,3)  @ bits 13..10  (16-amp groups; perm-gather fused for layers 1,2)
//   T2: pairs (4,5),(6,7),(8,9) @ bits 9..4 (64-amp thread-private group, 3 stages, no sync)
//   T3: pairs (10,11),(12,13) @ bits 3..0  (rotated float4 tiles; layer 2 folds measurement)
// CNOT ring = GF(2)-linear perm: folded into next T1's gather / final measurement (pfwd).

#define NW   14
#define DIM  16384
#define NT   256

typedef unsigned long long u64;

__device__ float4 g_mats[21][16];   // per wire-pair 4x4: {ur, ur, -ui, ui}

// ---------------- setup: build fused 4x4 gate matrices ----------------

struct cpx { float re, im; };
__device__ __forceinline__ cpx cmul(cpx a, cpx b){
    cpx r; r.re = a.re*b.re - a.im*b.im; r.im = a.re*b.im + a.im*b.re; return r;
}

__device__ void rotmat(const float* p, cpx U[2][2]){
    float cx = cosf(0.5f*p[0]), sx = sinf(0.5f*p[0]);
    float cy = cosf(0.5f*p[1]), sy = sinf(0.5f*p[1]);
    float cz = cosf(0.5f*p[2]), sz = sinf(0.5f*p[2]);
    cpx r00 = { cy*cx,  sy*sx};
    cpx r01 = {-sy*cx, -cy*sx};
    cpx r10 = { sy*cx, -cy*sx};
    cpx r11 = { cy*cx, -sy*sx};
    cpx e0 = {cz, -sz}, e1 = {cz, sz};
    U[0][0] = cmul(e0, r00); U[0][1] = cmul(e0, r01);
    U[1][0] = cmul(e1, r10); U[1][1] = cmul(e1, r11);
}

__global__ void setup_mats(const float* __restrict__ vp){
    int pid = threadIdx.x;
    if (pid >= 21) return;
    int l = pid / 7, k = pid % 7;
    cpx Ua[2][2], Ub[2][2];
    rotmat(vp + (l*NW + 2*k    )*3, Ua);
    rotmat(vp + (l*NW + 2*k + 1)*3, Ub);
    #pragma unroll
    for (int i = 0; i < 2; i++)
    #pragma unroll
    for (int j = 0; j < 2; j++)
    #pragma unroll
    for (int a = 0; a < 2; a++)
    #pragma unroll
    for (int c = 0; c < 2; c++){
        cpx m = cmul(Ua[i][a], Ub[j][c]);        // kron: wire 2k more significant
        g_mats[pid][(2*i + j)*4 + (2*a + c)] = make_float4(m.re, m.re, -m.im, m.im);
    }
}

// ---------------- packed f32x2 helpers ----------------

__device__ __forceinline__ u64 pk2(float lo, float hi){
    u64 r; asm("mov.b64 %0, {%1,%2};" : "=l"(r) : "f"(lo), "f"(hi)); return r;
}
__device__ __forceinline__ void upk2(u64 v, float& lo, float& hi){
    asm("mov.b64 {%0,%1}, %2;" : "=f"(lo), "=f"(hi) : "l"(v));
}
__device__ __forceinline__ u64 swp2(u64 v){
    u64 r;
    asm("{ .reg .b32 a,b; mov.b64 {a,b}, %1; mov.b64 %0, {b,a}; }" : "=l"(r) : "l"(v));
    return r;
}
__device__ __forceinline__ u64 f2(u64 a, u64 b, u64 c){
    u64 r; asm("fma.rn.f32x2 %0, %1, %2, %3;" : "=l"(r) : "l"(a), "l"(b), "l"(c)); return r;
}
__device__ __forceinline__ u64 m2(u64 a, u64 b){
    u64 r; asm("mul.rn.f32x2 %0, %1, %2;" : "=l"(r) : "l"(a), "l"(b)); return r;
}

struct Mat4 { u64 u[16], n[16]; };

__device__ __forceinline__ void loadmat(Mat4& M, int pair){
    #pragma unroll
    for (int e = 0; e < 16; e++){
        float4 f = __ldg(&g_mats[pair][e]);
        M.u[e] = pk2(f.x, f.y);
        M.n[e] = pk2(f.z, f.w);
    }
}

// in-place 4x4 complex matvec over amp[i0..i3] (packed (re,im))
__device__ __forceinline__ void applyGroup(const Mat4& M, u64* amp,
                                           int i0, int i1, int i2, int i3){
    u64 v0 = amp[i0], v1 = amp[i1], v2 = amp[i2], v3 = amp[i3];
    u64 s0 = swp2(v0), s1 = swp2(v1), s2 = swp2(v2), s3 = swp2(v3);
    u64 o0, o1, o2, o3;
    {
        u64 a = m2(M.u[0], v0); a = f2(M.n[0], s0, a);
        a = f2(M.u[1], v1, a);  a = f2(M.n[1], s1, a);
        a = f2(M.u[2], v2, a);  a = f2(M.n[2], s2, a);
        a = f2(M.u[3], v3, a);  a = f2(M.n[3], s3, a);
        o0 = a;
    }
    {
        u64 a = m2(M.u[4], v0); a = f2(M.n[4], s0, a);
        a = f2(M.u[5], v1, a);  a = f2(M.n[5], s1, a);
        a = f2(M.u[6], v2, a);  a = f2(M.n[6], s2, a);
        a = f2(M.u[7], v3, a);  a = f2(M.n[7], s3, a);
        o1 = a;
    }
    {
        u64 a = m2(M.u[8], v0);  a = f2(M.n[8], s0, a);
        a = f2(M.u[9], v1, a);   a = f2(M.n[9], s1, a);
        a = f2(M.u[10], v2, a);  a = f2(M.n[10], s2, a);
        a = f2(M.u[11], v3, a);  a = f2(M.n[11], s3, a);
        o2 = a;
    }
    {
        u64 a = m2(M.u[12], v0); a = f2(M.n[12], s0, a);
        a = f2(M.u[13], v1, a);  a = f2(M.n[13], s1, a);
        a = f2(M.u[14], v2, a);  a = f2(M.n[14], s2, a);
        a = f2(M.u[15], v3, a);  a = f2(M.n[15], s3, a);
        o3 = a;
    }
    amp[i0] = o0; amp[i1] = o1; amp[i2] = o2; amp[i3] = o3;
}

// ---------------- CNOT-ring permutation (GF2 linear) ----------------
__device__ __forceinline__ int pfwd(int i){
    int y = i;
    y ^= y >> 1; y ^= y >> 2; y ^= y >> 4; y ^= y >> 8;
    return (y & 0x1FFF) ^ ((((y ^ (i >> 13)) & 1) << 13));
}
__device__ __forceinline__ int pinv(int o){
    int t = o ^ (o >> 1);
    return (t & 0x1FFF) ^ (o & 0x2000) ^ ((o & 1) ? 0x3000 : 0);
}

// ---------------- passes ----------------

// T1 with fused perm-gather (layers 1,2): stage all 64 amps (read pinv), sync, apply+write.
__device__ __forceinline__ void passT1perm(float2* psi, int layer, int t){
    u64 amp[64];
    #pragma unroll
    for (int jj = 0; jj < 4; jj++){
        int gid = t + NT*jj;
        #pragma unroll
        for (int f = 0; f < 16; f++){
            float2 a = psi[pinv((f << 10) | gid)];
            amp[jj*16 + f] = pk2(a.x, a.y);
        }
    }
    __syncthreads();
    {
        Mat4 M; loadmat(M, layer*7 + 0);          // pair (0,1) @ bits 13,12
        #pragma unroll
        for (int jj = 0; jj < 4; jj++)
        #pragma unroll
        for (int q = 0; q < 4; q++)
            applyGroup(M, amp + jj*16, q, 4+q, 8+q, 12+q);
    }
    {
        Mat4 M; loadmat(M, layer*7 + 1);          // pair (2,3) @ bits 11,10
        #pragma unroll
        for (int jj = 0; jj < 4; jj++)
        #pragma unroll
        for (int q = 0; q < 4; q++)
            applyGroup(M, amp + jj*16, q<<2, (q<<2)|1, (q<<2)|2, (q<<2)|3);
    }
    #pragma unroll
    for (int jj = 0; jj < 4; jj++){
        int gid = t + NT*jj;
        #pragma unroll
        for (int f = 0; f < 16; f++){
            float x, y; upk2(amp[jj*16 + f], x, y);
            psi[(f << 10) | gid] = make_float2(x, y);
        }
    }
}

// T2: pairs (4,5),(6,7),(8,9) @ bits 9..4. One thread owns a full 64-amp group.
__device__ __forceinline__ void passT2(float2* psi, int layer, int t){
    const int base = ((t >> 4) << 10) | (t & 15);
    u64 amp[64];
    #pragma unroll
    for (int f = 0; f < 64; f++){
        float2 a = psi[base + (f << 4)];
        amp[f] = pk2(a.x, a.y);
    }
    {
        Mat4 M; loadmat(M, layer*7 + 2);          // pair (4,5) @ bits 9,8
        #pragma unroll
        for (int q = 0; q < 16; q++)
            applyGroup(M, amp, q, 16+q, 32+q, 48+q);
    }
    {
        Mat4 M; loadmat(M, layer*7 + 3);          // pair (6,7) @ bits 7,6
        #pragma unroll
        for (int h = 0; h < 4; h++)
        #pragma unroll
        for (int l2 = 0; l2 < 4; l2++)
            applyGroup(M, amp, (h<<4)|l2, (h<<4)|4|l2, (h<<4)|8|l2, (h<<4)|12|l2);
    }
    {
        Mat4 M; loadmat(M, layer*7 + 4);          // pair (8,9) @ bits 5,4
        #pragma unroll
        for (int q = 0; q < 16; q++)
            applyGroup(M, amp, q<<2, (q<<2)|1, (q<<2)|2, (q<<2)|3);
    }
    #pragma unroll
    for (int f = 0; f < 64; f++){
        float x, y; upk2(amp[f], x, y);
        psi[base + (f << 4)] = make_float2(x, y);
    }
}

// T3: pairs (10,11),(12,13) @ bits 3..0; rotated float4 16-amp tiles (layers 0,1).
__device__ __forceinline__ void passT3(float2* psi, int layer, int t){
    float4* p4 = reinterpret_cast<float4*>(psi);
    Mat4 A, B; loadmat(A, layer*7 + 5); loadmat(B, layer*7 + 6);
    const int rot = t & 7;
    #pragma unroll 1
    for (int tt = 0; tt < 4; tt++){
        int tile = t + NT*tt;
        u64 amp[16];
        #pragma unroll
        for (int r = 0; r < 8; r++){
            int rr = (r + rot) & 7;
            float4 q = p4[tile*8 + rr];
            amp[2*rr]   = pk2(q.x, q.y);
            amp[2*rr+1] = pk2(q.z, q.w);
        }
        #pragma unroll
        for (int q = 0; q < 4; q++)
            applyGroup(A, amp, q, 4+q, 8+q, 12+q);
        #pragma unroll
        for (int q = 0; q < 4; q++)
            applyGroup(B, amp, q<<2, (q<<2)|1, (q<<2)|2, (q<<2)|3);
        #pragma unroll
        for (int r = 0; r < 8; r++){
            int rr = (r + rot) & 7;
            float l0,h0,l1,h1;
            upk2(amp[2*rr],   l0, h0);
            upk2(amp[2*rr+1], l1, h1);
            p4[tile*8 + rr] = make_float4(l0, h0, l1, h1);
        }
    }
}

// T3 for layer 2: apply, then fold final-perm measurement in registers (no stores).
__device__ __forceinline__ void passT3meas(float2* psi, int t, float* zs){
    float4* p4 = reinterpret_cast<float4*>(psi);
    Mat4 A, B; loadmat(A, 2*7 + 5); loadmat(B, 2*7 + 6);
    const int rot = t & 7;
    #pragma unroll 1
    for (int tt = 0; tt < 4; tt++){
        int tile = t + NT*tt;
        u64 amp[16];
        #pragma unroll
        for (int r = 0; r < 8; r++){
            int rr = (r + rot) & 7;
            float4 q = p4[tile*8 + rr];
            amp[2*rr]   = pk2(q.x, q.y);
            amp[2*rr+1] = pk2(q.z, q.w);
        }
        #pragma unroll
        for (int q = 0; q < 4; q++)
            applyGroup(A, amp, q, 4+q, 8+q, 12+q);
        #pragma unroll
        for (int q = 0; q < 4; q++)
            applyGroup(B, amp, q<<2, (q<<2)|1, (q<<2)|2, (q<<2)|3);
        #pragma unroll
        for (int f = 0; f < 16; f++){
            float x, y; upk2(amp[f], x, y);
            float pr = x*x + y*y;
            unsigned pbits = __float_as_uint(pr);
            unsigned o = (unsigned)pfwd((tile << 4) | f);
            #pragma unroll
            for (int w = 0; w < NW; w++){
                unsigned m = (o << (18 + w)) & 0x80000000u;   // bit (13-w) -> sign
                zs[w] += __uint_as_float(pbits ^ m);
            }
        }
    }
}

// ---------------- main kernel ----------------

__global__ void __launch_bounds__(NT, 1)
qsim_kernel(const float* __restrict__ sr, const float* __restrict__ si,
            const float* __restrict__ hw, const float* __restrict__ hb,
            float* __restrict__ out)
{
    extern __shared__ float2 psi[];
    const int t = threadIdx.x;
    const int b = blockIdx.x;

    // ---- layer 0: T1 fused with global load (pairs (0,1),(2,3)) ----
    {
        Mat4 A, B; loadmat(A, 0); loadmat(B, 1);
        const float* srb = sr + (size_t)b * DIM;
        const float* sib = si + (size_t)b * DIM;
        #pragma unroll 1
        for (int jj = 0; jj < 4; jj++){
            int gid = t + NT*jj;
            u64 amp[16];
            #pragma unroll
            for (int f = 0; f < 16; f++){
                float re = __ldg(srb + (f << 10) + gid);
                float im = __ldg(sib + (f << 10) + gid);
                amp[f] = pk2(re, im);
            }
            #pragma unroll
            for (int q = 0; q < 4; q++)
                applyGroup(A, amp, q, 4+q, 8+q, 12+q);
            #pragma unroll
            for (int q = 0; q < 4; q++)
                applyGroup(B, amp, q<<2, (q<<2)|1, (q<<2)|2, (q<<2)|3);
            #pragma unroll
            for (int f = 0; f < 16; f++){
                float x, y; upk2(amp[f], x, y);
                psi[(f << 10) + gid] = make_float2(x, y);
            }
        }
    }
    __syncthreads();
    passT2(psi, 0, t);
    __syncthreads();
    passT3(psi, 0, t);
    __syncthreads();

    // ---- layer 1 (T1 gathers through CNOT-ring perm of layer 0) ----
    passT1perm(psi, 1, t);
    __syncthreads();
    passT2(psi, 1, t);
    __syncthreads();
    passT3(psi, 1, t);
    __syncthreads();

    // ---- layer 2 ----
    passT1perm(psi, 2, t);
    __syncthreads();
    passT2(psi, 2, t);
    __syncthreads();

    // ---- layer 2 T3 + measurement (final perm folded via pfwd) ----
    float zs[NW];
    #pragma unroll
    for (int w = 0; w < NW; w++) zs[w] = 0.f;
    passT3meas(psi, t, zs);

    // warp reduce
    #pragma unroll
    for (int off = 16; off > 0; off >>= 1)
        #pragma unroll
        for (int w = 0; w < NW; w++)
            zs[w] += __shfl_down_sync(0xffffffffu, zs[w], off);
    __syncthreads();                       // all psi reads done; reuse as scratch
    float* red = (float*)psi;
    const int NWARP = NT/32;
    int lane = t & 31, wid = t >> 5;
    if (lane == 0){
        #pragma unroll
        for (int w = 0; w < NW; w++) red[w*NWARP + wid] = zs[w];
    }
    __syncthreads();
    if (t == 0){
        float acc = __ldg(hb);
        #pragma unroll
        for (int w = 0; w < NW; w++){
            float f = 0.f;
            #pragma unroll
            for (int r = 0; r < NWARP; r++) f += red[w*NWARP + r];
            acc += f * __ldg(hw + w);
        }
        out[b] = acc;
    }
}

// ---------------- launch ----------------

extern "C" void kernel_launch(void* const* d_in, const int* in_sizes, int n_in,
                              void* d_out, int out_size)
{
    const float* sr = (const float*)d_in[0];
    const float* si = (const float*)d_in[1];
    const float* vp = (const float*)d_in[2];
    const float* hw = (const float*)d_in[3];
    const float* hb = (const float*)d_in[4];
    float* out = (float*)d_out;

    cudaFuncSetAttribute(qsim_kernel, cudaFuncAttributeMaxDynamicSharedMemorySize, 131072);

    setup_mats<<<1, 32>>>(vp);

    int B = in_sizes[0] / DIM;
    qsim_kernel<<<B, NT, 131072>>>(sr, si, hw, hb, out);
}